// round 12
// baseline (speedup 1.0000x reference)
#include <cuda_runtime.h>
#include <cuda_fp16.h>
#include <cstdint>
#include <cfloat>

#define KC 120
#define DC 128
#define NMAX 262144
#define TILE_M 128
#define SROW 121          // S row stride (floats), odd => conflict-free
#define KCH2 64           // dims per staging chunk
#define XST 72            // f16 row stride (64 + 8 pad) => conflict-free frag loads

typedef unsigned long long u64;

// ---------------- device scratch ----------------
__device__ float  g_cent[2][KC * DC];
__device__ float  g_csq[2][KC];
__device__ float  g_sums[KC * DC];
__device__ float  g_counts[KC];
__device__ int    g_labels[2][NMAX];
__device__ double g_acc[2];
// pre-split fp16 copies (hi/lo), built once per replay
__device__ __half g_xh[2][NMAX * DC];
__device__ __half g_xl[2][NMAX * DC];
__device__ __half g_ch[2][KC * DC];
__device__ __half g_cl[2][KC * DC];

// single dynamic-smem symbol shared by all kernels (cast locally)
extern __shared__ char dyn_smem[];

// ---------------- smem layout (gemm kernel) ----------------
#define OFF_CSQ 0                       // 128 floats
#define OFF_RED 512                     // 8 floats
#define OFF_XH  1024                    // 128 x 72 f16 = 18432 B
#define OFF_XL  (1024 + 18432)
#define OFF_CH  (1024 + 2 * 18432)
#define OFF_CL  (1024 + 3 * 18432)
#define OFF_S   1024                    // epilogue S overlaps staging
#define GEMM_SMEM (1024 + 4 * 18432)    // 74752 B

// m16n8k16 f16 mma, fp32 accumulate
__device__ __forceinline__ void mma16816(float* c, const uint32_t* a,
                                         uint32_t b0, uint32_t b1) {
    asm volatile(
        "mma.sync.aligned.m16n8k16.row.col.f32.f16.f16.f32 "
        "{%0,%1,%2,%3}, {%4,%5,%6,%7}, {%8,%9}, {%0,%1,%2,%3};"
        : "+f"(c[0]), "+f"(c[1]), "+f"(c[2]), "+f"(c[3])
        : "r"(a[0]), "r"(a[1]), "r"(a[2]), "r"(a[3]), "r"(b0), "r"(b1));
}

// ================= one-time fp16 hi/lo pre-split of X =================
__global__ __launch_bounds__(256)
void preconvert_kernel(const float* __restrict__ x, int set, int total4) {
    int idx = blockIdx.x * 256 + threadIdx.x;    // float4 index
    if (idx >= total4) return;
    float4 v = ((const float4*)x)[idx];
    __half hx = __float2half_rn(v.x), hy = __float2half_rn(v.y);
    __half hz = __float2half_rn(v.z), hw = __float2half_rn(v.w);
    __half2* dh = (__half2*)(g_xh[set]) + idx * 2;
    dh[0] = __halves2half2(hx, hy);
    dh[1] = __halves2half2(hz, hw);
    __half2* dl = (__half2*)(g_xl[set]) + idx * 2;
    dl[0] = __halves2half2(__float2half_rn(v.x - __half2float(hx)),
                           __float2half_rn(v.y - __half2float(hy)));
    dl[1] = __halves2half2(__float2half_rn(v.z - __half2float(hz)),
                           __float2half_rn(v.w - __half2float(hw)));
}

// ================= fp16-split tensor-core GEMM + head =================
// dot[p][k] = x_p (features xset) . c_k (centroids cset); 128-pt tile vs 120 clusters.
// mode 0 (xset==cset): argmin_k (csq[k] - 2*dot) -> g_labels[cset]
// mode 1: CE_i = logsumexp(2.5*dot) - 2.5*dot[lab_i], lab from g_labels[cset] -> g_acc[aidx]
__global__ __launch_bounds__(256, 2)
void gemm_head_kernel(int xset, int cset, int mode, int aidx, int N) {
    char* sm = dyn_smem;
    float*  csq_s = (float*)(sm + OFF_CSQ);
    __half* xh = (__half*)(sm + OFF_XH);
    __half* xl = (__half*)(sm + OFF_XL);
    __half* chh = (__half*)(sm + OFF_CH);
    __half* cll = (__half*)(sm + OFF_CL);
    float*  S  = (float*)(sm + OFF_S);

    int tid = threadIdx.x;
    int lane = tid & 31, g = lane >> 2, t = lane & 3;
    int warp = tid >> 5;
    int wm = warp >> 1;            // 0..3  -> rows wm*32
    int wn = warp & 1;             // 0..1  -> cols wn*64
    int pm = wm * 32;
    int nb = wn * 64;

    if (mode == 0 && tid < KC) csq_s[tid] = g_csq[cset][tid];

    int tile0 = blockIdx.x * TILE_M;

    float acc[2][8][4];
    #pragma unroll
    for (int mi = 0; mi < 2; mi++)
        #pragma unroll
        for (int ni = 0; ni < 8; ni++)
            #pragma unroll
            for (int q = 0; q < 4; q++) acc[mi][ni][q] = 0.0f;

    const uint32_t* XH32 = (const uint32_t*)xh;
    const uint32_t* XL32 = (const uint32_t*)xl;
    const uint32_t* CH32 = (const uint32_t*)chh;
    const uint32_t* CL32 = (const uint32_t*)cll;

    for (int ch = 0; ch < 2; ch++) {
        int k0 = ch * KCH2;

        // ---- stage: pure uint4 copies of pre-split halves ----
        #pragma unroll
        for (int it = 0; it < 4; it++) {
            int idx = tid + 256 * it;            // 0..1023
            int p = idx >> 3, s = idx & 7;       // row, 16B-slot
            int pc = tile0 + p; if (pc >= N) pc = N - 1;
            const uint4* sxh = (const uint4*)(g_xh[xset] + (size_t)pc * DC + k0) + s;
            const uint4* sxl = (const uint4*)(g_xl[xset] + (size_t)pc * DC + k0) + s;
            *(uint4*)(xh + p * XST + s * 8) = *sxh;
            *(uint4*)(xl + p * XST + s * 8) = *sxl;
            uint4 vh = make_uint4(0u, 0u, 0u, 0u), vl = vh;
            if (p < KC) {
                vh = *((const uint4*)(g_ch[cset] + p * DC + k0) + s);
                vl = *((const uint4*)(g_cl[cset] + p * DC + k0) + s);
            }
            *(uint4*)(chh + p * XST + s * 8) = vh;
            *(uint4*)(cll + p * XST + s * 8) = vl;
        }
        __syncthreads();

        // ---- mma over 4 k-steps of 16 ----
        #pragma unroll
        for (int ks = 0; ks < 4; ks++) {
            int kk = ks * 16;
            uint32_t ah[2][4], al[2][4];
            #pragma unroll
            for (int mi = 0; mi < 2; mi++) {
                int p0 = pm + mi * 16 + g;
                int i00 = p0 * (XST / 2) + (kk + 2 * t) / 2;   // u32 units
                int i80 = i00 + 8 * (XST / 2);
                ah[mi][0] = XH32[i00];     ah[mi][1] = XH32[i80];
                ah[mi][2] = XH32[i00 + 4]; ah[mi][3] = XH32[i80 + 4];
                al[mi][0] = XL32[i00];     al[mi][1] = XL32[i80];
                al[mi][2] = XL32[i00 + 4]; al[mi][3] = XL32[i80 + 4];
            }
            #pragma unroll
            for (int ni = 0; ni < 8; ni++) {
                int n = nb + ni * 8 + g;
                int j0 = n * (XST / 2) + (kk + 2 * t) / 2;
                uint32_t bh0 = CH32[j0], bh1 = CH32[j0 + 4];
                uint32_t bl0 = CL32[j0], bl1 = CL32[j0 + 4];
                #pragma unroll
                for (int mi = 0; mi < 2; mi++) {
                    mma16816(acc[mi][ni], ah[mi], bh0, bh1);   // hi*hi
                    mma16816(acc[mi][ni], ah[mi], bl0, bl1);   // hi*lo
                    mma16816(acc[mi][ni], al[mi], bh0, bh1);   // lo*hi
                }
            }
        }
        __syncthreads();   // staging region about to be reused
    }

    // ---- write S[p][n] (skip pad cols 120..127: wn==1 && ni==7) ----
    #pragma unroll
    for (int mi = 0; mi < 2; mi++) {
        int p0 = pm + mi * 16 + g;
        #pragma unroll
        for (int ni = 0; ni < 8; ni++) {
            if (wn == 1 && ni == 7) continue;
            int n0 = nb + ni * 8 + 2 * t;
            S[p0 * SROW + n0]           = acc[mi][ni][0];
            S[p0 * SROW + n0 + 1]       = acc[mi][ni][1];
            S[(p0 + 8) * SROW + n0]     = acc[mi][ni][2];
            S[(p0 + 8) * SROW + n0 + 1] = acc[mi][ni][3];
        }
    }
    __syncthreads();

    // ---- head: one thread per point (threads 0..127) ----
    int p = tile0 + tid;
    bool valid = (tid < TILE_M) && (p < N);

    if (mode == 0) {
        if (valid) {
            const float* Sp = S + tid * SROW;
            float best = FLT_MAX;
            int bi = 0;
            #pragma unroll 4
            for (int k = 0; k < KC; k++) {
                float dist = csq_s[k] - 2.0f * Sp[k];
                if (dist < best) { best = dist; bi = k; }   // strict < => first-index ties
            }
            g_labels[cset][p] = bi;
        }
    } else {
        float ce = 0.0f;
        if (valid) {
            const float* Sp = S + tid * SROW;
            int lab = g_labels[cset][p];
            float m = -3.0e38f, ss = 0.0f, lgl = 0.0f;
            #pragma unroll 4
            for (int k = 0; k < KC; k++) {
                float lg = 2.5f * Sp[k];          // / CLD_T = 0.4
                if (k == lab) lgl = lg;
                float nm = fmaxf(m, lg);
                ss = ss * __expf(m - nm) + __expf(lg - nm);
                m = nm;
            }
            ce = m + logf(ss) - lgl;
        }
        #pragma unroll
        for (int o = 16; o > 0; o >>= 1) ce += __shfl_down_sync(0xffffffffu, ce, o);
        float* red = (float*)(sm + OFF_RED);
        if ((tid & 31) == 0) red[tid >> 5] = ce;
        __syncthreads();
        if (tid == 0) {
            float tt = red[0] + red[1] + red[2] + red[3] +
                       red[4] + red[5] + red[6] + red[7];
            atomicAdd(&g_acc[aidx], (double)tt);
        }
    }
}

// ================= centroid init / update (+ fp16 hi/lo split) =================
__global__ void centroid_kernel(const float* __restrict__ x, int set, int mode) {
    int k = blockIdx.x;
    int d = threadIdx.x;
    float c;
    if (mode == 0) {
        c = x[k * DC + d];
    } else {
        float cnt = g_counts[k];
        if (cnt == 0.0f) cnt = 1.0f;
        c = g_sums[k * DC + d] / cnt;
    }
    g_cent[set][k * DC + d] = c;
    __half hc = __float2half_rn(c);
    g_ch[set][k * DC + d] = hc;
    g_cl[set][k * DC + d] = __float2half_rn(c - __half2float(hc));
    g_sums[k * DC + d] = 0.0f;
    if (d == 0) g_counts[k] = 0.0f;

    float v = c * c;
    #pragma unroll
    for (int o = 16; o > 0; o >>= 1) v += __shfl_down_sync(0xffffffffu, v, o);
    __shared__ float rsm[4];
    if ((d & 31) == 0) rsm[d >> 5] = v;
    __syncthreads();
    if (d == 0) g_csq[set][k] = rsm[0] + rsm[1] + rsm[2] + rsm[3];
}

// ================= scatter reduce =================
__global__ __launch_bounds__(256, 1)
void reduce_kernel(const float* __restrict__ x, int set, int N) {
    float* smf = (float*)dyn_smem;
    float* sumA = smf;
    float* sumB = smf + KC * DC;
    float* scnt = smf + 2 * KC * DC;

    int tid = threadIdx.x;
    for (int i = tid; i < 2 * KC * DC; i += 256) smf[i] = 0.0f;
    for (int i = tid; i < KC; i += 256) scnt[i] = 0.0f;
    __syncthreads();

    const int* __restrict__ lab = g_labels[set];
    int G = gridDim.x;
    int per = (N + G - 1) / G;
    int p0 = blockIdx.x * per;
    int p1 = min(N, p0 + per);

    int half = tid >> 7;
    int d = tid & 127;
    float* mysum = half ? sumB : sumA;
    int pm = p0 + ((p1 - p0) >> 1);
    int qs = half ? pm : p0;
    int qe = half ? p1 : pm;

    int p = qs;
    for (; p + 4 <= qe; p += 4) {
        int l0 = lab[p], l1 = lab[p + 1], l2 = lab[p + 2], l3 = lab[p + 3];
        float v0 = x[(size_t)(p)     * DC + d];
        float v1 = x[(size_t)(p + 1) * DC + d];
        float v2 = x[(size_t)(p + 2) * DC + d];
        float v3 = x[(size_t)(p + 3) * DC + d];
        mysum[l0 * DC + d] += v0;
        mysum[l1 * DC + d] += v1;
        mysum[l2 * DC + d] += v2;
        mysum[l3 * DC + d] += v3;
    }
    for (; p < qe; ++p)
        mysum[lab[p] * DC + d] += x[(size_t)p * DC + d];

    for (int q = p0 + tid; q < p1; q += 256)
        atomicAdd(&scnt[lab[q]], 1.0f);
    __syncthreads();

    for (int i = tid; i < KC * DC; i += 256)
        atomicAdd(&g_sums[i], sumA[i] + sumB[i]);
    for (int i = tid; i < KC; i += 256)
        atomicAdd(&g_counts[i], scnt[i]);
}

__global__ void zero_acc_kernel() {
    if (threadIdx.x < 2) g_acc[threadIdx.x] = 0.0;
}
__global__ void finalize_kernel(float* out, int N) {
    out[0] = (float)((g_acc[0] + g_acc[1]) / (2.0 * (double)N));
}

// ================= launch =================
extern "C" void kernel_launch(void* const* d_in, const int* in_sizes, int n_in,
                              void* d_out, int out_size) {
    const float* f1 = (const float*)d_in[0];
    const float* f2 = (const float*)d_in[1];
    int N = in_sizes[0] / DC;

    const int REDUCE_SMEM = (2 * KC * DC + KC) * (int)sizeof(float);

    cudaFuncSetAttribute(gemm_head_kernel, cudaFuncAttributeMaxDynamicSharedMemorySize, GEMM_SMEM);
    cudaFuncSetAttribute(reduce_kernel, cudaFuncAttributeMaxDynamicSharedMemorySize, REDUCE_SMEM);

    int ggrid = (N + TILE_M - 1) / TILE_M;
    int total4 = N * DC / 4;
    int pgrid = (total4 + 255) / 256;

    preconvert_kernel<<<pgrid, 256>>>(f1, 0, total4);
    preconvert_kernel<<<pgrid, 256>>>(f2, 1, total4);

    for (int s = 0; s < 2; ++s) {
        const float* x = s ? f2 : f1;
        centroid_kernel<<<KC, DC>>>(x, s, 0);
        for (int it = 0; it < 5; ++it) {
            gemm_head_kernel<<<ggrid, 256, GEMM_SMEM>>>(s, s, 0, 0, N);
            reduce_kernel<<<128, 256, REDUCE_SMEM>>>(x, s, N);
            centroid_kernel<<<KC, DC>>>(nullptr, s, 1);
        }
    }
    zero_acc_kernel<<<1, 32>>>();
    gemm_head_kernel<<<ggrid, 256, GEMM_SMEM>>>(0, 1, 1, 0, N);  // X=f1 vs c2/cl2
    gemm_head_kernel<<<ggrid, 256, GEMM_SMEM>>>(1, 0, 1, 1, N);  // X=f2 vs c1/cl1
    finalize_kernel<<<1, 1>>>((float*)d_out, N);
}

// round 13
// speedup vs baseline: 1.2505x; 1.2505x over previous
#include <cuda_runtime.h>
#include <cuda_fp16.h>
#include <cstdint>
#include <cfloat>

#define KC 120
#define DC 128
#define NMAX 262144
#define TILE_M 128
#define SROW 121          // S row stride (floats), odd => conflict-free
#define KCH2 64           // dims per staging chunk
#define XST 72            // f16 row stride (64 + 8 pad) => conflict-free ldmatrix

typedef unsigned long long u64;

// ---------------- device scratch ----------------
__device__ float  g_cent[2][KC * DC];
__device__ float  g_csq[2][KC];
__device__ float  g_sums[KC * DC];
__device__ float  g_counts[KC];
__device__ int    g_labels[2][NMAX];
__device__ double g_acc[2];
// pre-split fp16 copies (hi/lo), built once per replay
__device__ __half g_xh[2][NMAX * DC];
__device__ __half g_xl[2][NMAX * DC];
__device__ __half g_ch[2][KC * DC];
__device__ __half g_cl[2][KC * DC];

// single dynamic-smem symbol shared by all kernels (cast locally)
extern __shared__ char dyn_smem[];

// ---------------- smem layout (gemm kernel) ----------------
#define OFF_CSQ 0                       // 128 floats
#define OFF_RED 512                     // 8 floats
#define OFF_XH  1024                    // 128 x 72 f16 = 18432 B
#define OFF_XL  (1024 + 18432)
#define OFF_CH  (1024 + 2 * 18432)
#define OFF_CL  (1024 + 3 * 18432)
#define OFF_S   1024                    // epilogue S overlaps staging
#define GEMM_SMEM (1024 + 4 * 18432)    // 74752 B

// m16n8k16 f16 mma, fp32 accumulate
__device__ __forceinline__ void mma16816(float* c, const uint32_t* a,
                                         uint32_t b0, uint32_t b1) {
    asm volatile(
        "mma.sync.aligned.m16n8k16.row.col.f32.f16.f16.f32 "
        "{%0,%1,%2,%3}, {%4,%5,%6,%7}, {%8,%9}, {%0,%1,%2,%3};"
        : "+f"(c[0]), "+f"(c[1]), "+f"(c[2]), "+f"(c[3])
        : "r"(a[0]), "r"(a[1]), "r"(a[2]), "r"(a[3]), "r"(b0), "r"(b1));
}
__device__ __forceinline__ void ldsm_x4(uint32_t* r, uint32_t addr) {
    asm volatile("ldmatrix.sync.aligned.m8n8.x4.shared.b16 {%0,%1,%2,%3}, [%4];"
        : "=r"(r[0]), "=r"(r[1]), "=r"(r[2]), "=r"(r[3]) : "r"(addr));
}
__device__ __forceinline__ void ldsm_x2(uint32_t& r0, uint32_t& r1, uint32_t addr) {
    asm volatile("ldmatrix.sync.aligned.m8n8.x2.shared.b16 {%0,%1}, [%2];"
        : "=r"(r0), "=r"(r1) : "r"(addr));
}

// ================= one-time fp16 hi/lo pre-split of X =================
__global__ __launch_bounds__(256)
void preconvert_kernel(const float* __restrict__ x, int set, int total4) {
    int idx = blockIdx.x * 256 + threadIdx.x;    // float4 index
    if (idx >= total4) return;
    float4 v = ((const float4*)x)[idx];
    __half hx = __float2half_rn(v.x), hy = __float2half_rn(v.y);
    __half hz = __float2half_rn(v.z), hw = __float2half_rn(v.w);
    __half2* dh = (__half2*)(g_xh[set]) + idx * 2;
    dh[0] = __halves2half2(hx, hy);
    dh[1] = __halves2half2(hz, hw);
    __half2* dl = (__half2*)(g_xl[set]) + idx * 2;
    dl[0] = __halves2half2(__float2half_rn(v.x - __half2float(hx)),
                           __float2half_rn(v.y - __half2float(hy)));
    dl[1] = __halves2half2(__float2half_rn(v.z - __half2float(hz)),
                           __float2half_rn(v.w - __half2float(hw)));
}

// ================= fp16-split tensor-core GEMM + head =================
// dot[p][k] = x_p (features xset) . c_k (centroids cset); 128-pt tile vs 120 clusters.
// mode 0 (xset==cset): argmin_k (csq[k] - 2*dot) -> g_labels[cset]
// mode 1: CE_i = logsumexp(2.5*dot) - 2.5*dot[lab_i], lab from g_labels[cset] -> g_acc[aidx]
__global__ __launch_bounds__(256, 2)
void gemm_head_kernel(int xset, int cset, int mode, int aidx, int N) {
    char* sm = dyn_smem;
    float*  csq_s = (float*)(sm + OFF_CSQ);
    __half* xh = (__half*)(sm + OFF_XH);
    __half* xl = (__half*)(sm + OFF_XL);
    __half* chh = (__half*)(sm + OFF_CH);
    __half* cll = (__half*)(sm + OFF_CL);
    float*  S  = (float*)(sm + OFF_S);

    int tid = threadIdx.x;
    int lane = tid & 31, g = lane >> 2, t = lane & 3;
    int warp = tid >> 5;
    int wm = warp >> 1;            // 0..3  -> rows wm*32
    int wn = warp & 1;             // 0..1  -> cols wn*64
    int pm = wm * 32;
    int nb = wn * 64;

    if (mode == 0 && tid < KC) csq_s[tid] = g_csq[cset][tid];

    int tile0 = blockIdx.x * TILE_M;

    float acc[2][8][4];
    #pragma unroll
    for (int mi = 0; mi < 2; mi++)
        #pragma unroll
        for (int ni = 0; ni < 8; ni++)
            #pragma unroll
            for (int q = 0; q < 4; q++) acc[mi][ni][q] = 0.0f;

    uint32_t xh_s = (uint32_t)__cvta_generic_to_shared(xh);
    uint32_t xl_s = (uint32_t)__cvta_generic_to_shared(xl);
    uint32_t ch_s = (uint32_t)__cvta_generic_to_shared(chh);
    uint32_t cl_s = (uint32_t)__cvta_generic_to_shared(cll);

    // ldmatrix per-lane row/col selectors
    int arow  = ((lane >> 3) & 1) * 8 + (lane & 7);   // A: + pm + mi*16
    int acol8 = ((lane >> 4) & 1) * 8;                // A: k sub-tile
    int bl15  = lane & 15;
    int brow  = bl15 & 7;                             // B: + nb + ni*8
    int bcol8 = ((bl15 >> 3) & 1) * 8;                // B: k sub-tile

    for (int ch = 0; ch < 2; ch++) {
        int k0 = ch * KCH2;

        // ---- stage: pure uint4 copies of pre-split halves ----
        #pragma unroll
        for (int it = 0; it < 4; it++) {
            int idx = tid + 256 * it;            // 0..1023
            int p = idx >> 3, s = idx & 7;       // row, 16B-slot
            int pc = tile0 + p; if (pc >= N) pc = N - 1;
            const uint4* sxh = (const uint4*)(g_xh[xset] + (size_t)pc * DC + k0) + s;
            const uint4* sxl = (const uint4*)(g_xl[xset] + (size_t)pc * DC + k0) + s;
            *(uint4*)(xh + p * XST + s * 8) = *sxh;
            *(uint4*)(xl + p * XST + s * 8) = *sxl;
            uint4 vh = make_uint4(0u, 0u, 0u, 0u), vl = vh;
            if (p < KC) {
                vh = *((const uint4*)(g_ch[cset] + p * DC + k0) + s);
                vl = *((const uint4*)(g_cl[cset] + p * DC + k0) + s);
            }
            *(uint4*)(chh + p * XST + s * 8) = vh;
            *(uint4*)(cll + p * XST + s * 8) = vl;
        }
        __syncthreads();

        // ---- mma over 4 k-steps of 16, ldmatrix fragments ----
        #pragma unroll
        for (int ks = 0; ks < 4; ks++) {
            int kk = ks * 16;
            uint32_t ah[2][4], al[2][4];
            #pragma unroll
            for (int mi = 0; mi < 2; mi++) {
                uint32_t aoff = (uint32_t)(((pm + mi * 16 + arow) * XST + kk + acol8) * 2);
                ldsm_x4(ah[mi], xh_s + aoff);
                ldsm_x4(al[mi], xl_s + aoff);
            }
            #pragma unroll
            for (int ni = 0; ni < 8; ni++) {
                uint32_t boff = (uint32_t)(((nb + ni * 8 + brow) * XST + kk + bcol8) * 2);
                uint32_t bh0, bh1, bl0, bl1;
                ldsm_x2(bh0, bh1, ch_s + boff);
                ldsm_x2(bl0, bl1, cl_s + boff);
                #pragma unroll
                for (int mi = 0; mi < 2; mi++) {
                    mma16816(acc[mi][ni], ah[mi], bh0, bh1);   // hi*hi
                    mma16816(acc[mi][ni], ah[mi], bl0, bl1);   // hi*lo
                    mma16816(acc[mi][ni], al[mi], bh0, bh1);   // lo*hi
                }
            }
        }
        __syncthreads();   // staging region about to be reused
    }

    // ---- write S[p][n] (skip pad cols 120..127: wn==1 && ni==7) ----
    #pragma unroll
    for (int mi = 0; mi < 2; mi++) {
        int p0 = pm + mi * 16 + g;
        #pragma unroll
        for (int ni = 0; ni < 8; ni++) {
            if (wn == 1 && ni == 7) continue;
            int n0 = nb + ni * 8 + 2 * t;
            S[p0 * SROW + n0]           = acc[mi][ni][0];
            S[p0 * SROW + n0 + 1]       = acc[mi][ni][1];
            S[(p0 + 8) * SROW + n0]     = acc[mi][ni][2];
            S[(p0 + 8) * SROW + n0 + 1] = acc[mi][ni][3];
        }
    }
    __syncthreads();

    // ---- head: one thread per point (threads 0..127) ----
    int p = tile0 + tid;
    bool valid = (tid < TILE_M) && (p < N);

    if (mode == 0) {
        if (valid) {
            const float* Sp = S + tid * SROW;
            float best = FLT_MAX;
            int bi = 0;
            #pragma unroll 4
            for (int k = 0; k < KC; k++) {
                float dist = csq_s[k] - 2.0f * Sp[k];
                if (dist < best) { best = dist; bi = k; }   // strict < => first-index ties
            }
            g_labels[cset][p] = bi;
        }
    } else {
        float ce = 0.0f;
        if (valid) {
            const float* Sp = S + tid * SROW;
            int lab = g_labels[cset][p];
            float m = -3.0e38f, ss = 0.0f, lgl = 0.0f;
            #pragma unroll 4
            for (int k = 0; k < KC; k++) {
                float lg = 2.5f * Sp[k];          // / CLD_T = 0.4
                if (k == lab) lgl = lg;
                float nm = fmaxf(m, lg);
                ss = ss * __expf(m - nm) + __expf(lg - nm);
                m = nm;
            }
            ce = m + logf(ss) - lgl;
        }
        #pragma unroll
        for (int o = 16; o > 0; o >>= 1) ce += __shfl_down_sync(0xffffffffu, ce, o);
        float* red = (float*)(sm + OFF_RED);
        if ((tid & 31) == 0) red[tid >> 5] = ce;
        __syncthreads();
        if (tid == 0) {
            float tt = red[0] + red[1] + red[2] + red[3] +
                       red[4] + red[5] + red[6] + red[7];
            atomicAdd(&g_acc[aidx], (double)tt);
        }
    }
}

// ================= centroid init / update (+ fp16 hi/lo split) =================
__global__ void centroid_kernel(const float* __restrict__ x, int set, int mode) {
    int k = blockIdx.x;
    int d = threadIdx.x;
    float c;
    if (mode == 0) {
        c = x[k * DC + d];
    } else {
        float cnt = g_counts[k];
        if (cnt == 0.0f) cnt = 1.0f;
        c = g_sums[k * DC + d] / cnt;
    }
    g_cent[set][k * DC + d] = c;
    __half hc = __float2half_rn(c);
    g_ch[set][k * DC + d] = hc;
    g_cl[set][k * DC + d] = __float2half_rn(c - __half2float(hc));
    g_sums[k * DC + d] = 0.0f;
    if (d == 0) g_counts[k] = 0.0f;

    float v = c * c;
    #pragma unroll
    for (int o = 16; o > 0; o >>= 1) v += __shfl_down_sync(0xffffffffu, v, o);
    __shared__ float rsm[4];
    if ((d & 31) == 0) rsm[d >> 5] = v;
    __syncthreads();
    if (d == 0) g_csq[set][k] = rsm[0] + rsm[1] + rsm[2] + rsm[3];
}

// ================= scatter reduce (batch-16 MLP, smem labels) =================
#define RGRID 148
#define PERMAX 2048
#define REDUCE_SMEM ((2 * KC * DC + 128 + PERMAX) * 4)

__global__ __launch_bounds__(256, 1)
void reduce_kernel(const float* __restrict__ x, int set, int N) {
    float* smf = (float*)dyn_smem;
    float* sumA = smf;                         // KC*DC
    float* sumB = smf + KC * DC;               // KC*DC
    float* scnt = smf + 2 * KC * DC;           // 128 (120 used)
    int*   slab = (int*)(smf + 2 * KC * DC + 128);

    int tid = threadIdx.x;
    for (int i = tid; i < 2 * KC * DC; i += 256) smf[i] = 0.0f;
    for (int i = tid; i < 128; i += 256) scnt[i] = 0.0f;

    const int* __restrict__ lab = g_labels[set];
    int G = gridDim.x;
    int per = (N + G - 1) / G;
    int p0 = blockIdx.x * per;
    int cnt = min(N, p0 + per) - p0;
    if (cnt < 0) cnt = 0;

    for (int i = tid; i < cnt; i += 256) slab[i] = lab[p0 + i];
    __syncthreads();

    int half = tid >> 7;       // 0 or 1
    int d = tid & 127;
    float* mysum = half ? sumB : sumA;
    int mid = cnt >> 1;
    int qs = half ? mid : 0;
    int qe = half ? cnt : mid;

    const float* __restrict__ xb = x + (size_t)p0 * DC + d;
    int q = qs;
    for (; q + 16 <= qe; q += 16) {
        float v[16];
        #pragma unroll
        for (int i = 0; i < 16; i++)
            v[i] = __ldg(xb + (size_t)(q + i) * DC);
        int l[16];
        #pragma unroll
        for (int i = 0; i < 16; i++) l[i] = slab[q + i];
        #pragma unroll
        for (int i = 0; i < 16; i++)
            mysum[l[i] * DC + d] += v[i];
    }
    for (; q < qe; ++q)
        mysum[slab[q] * DC + d] += __ldg(xb + (size_t)q * DC);

    // counts (spread smem atomics over staged labels)
    for (int i = tid; i < cnt; i += 256)
        atomicAdd(&scnt[slab[i]], 1.0f);
    __syncthreads();

    for (int i = tid; i < KC * DC; i += 256)
        atomicAdd(&g_sums[i], sumA[i] + sumB[i]);
    for (int i = tid; i < KC; i += 256)
        atomicAdd(&g_counts[i], scnt[i]);
}

__global__ void zero_acc_kernel() {
    if (threadIdx.x < 2) g_acc[threadIdx.x] = 0.0;
}
__global__ void finalize_kernel(float* out, int N) {
    out[0] = (float)((g_acc[0] + g_acc[1]) / (2.0 * (double)N));
}

// ================= launch =================
extern "C" void kernel_launch(void* const* d_in, const int* in_sizes, int n_in,
                              void* d_out, int out_size) {
    const float* f1 = (const float*)d_in[0];
    const float* f2 = (const float*)d_in[1];
    int N = in_sizes[0] / DC;

    cudaFuncSetAttribute(gemm_head_kernel, cudaFuncAttributeMaxDynamicSharedMemorySize, GEMM_SMEM);
    cudaFuncSetAttribute(reduce_kernel, cudaFuncAttributeMaxDynamicSharedMemorySize, REDUCE_SMEM);

    int ggrid = (N + TILE_M - 1) / TILE_M;
    int total4 = N * DC / 4;
    int pgrid = (total4 + 255) / 256;

    preconvert_kernel<<<pgrid, 256>>>(f1, 0, total4);
    preconvert_kernel<<<pgrid, 256>>>(f2, 1, total4);

    for (int s = 0; s < 2; ++s) {
        const float* x = s ? f2 : f1;
        centroid_kernel<<<KC, DC>>>(x, s, 0);
        for (int it = 0; it < 5; ++it) {
            gemm_head_kernel<<<ggrid, 256, GEMM_SMEM>>>(s, s, 0, 0, N);
            reduce_kernel<<<RGRID, 256, REDUCE_SMEM>>>(x, s, N);
            centroid_kernel<<<KC, DC>>>(nullptr, s, 1);
        }
    }
    zero_acc_kernel<<<1, 32>>>();
    gemm_head_kernel<<<ggrid, 256, GEMM_SMEM>>>(0, 1, 1, 0, N);  // X=f1 vs c2/cl2
    gemm_head_kernel<<<ggrid, 256, GEMM_SMEM>>>(1, 0, 1, 1, N);  // X=f2 vs c1/cl1
    finalize_kernel<<<1, 1>>>((float*)d_out, N);
}

// round 14
// speedup vs baseline: 1.5706x; 1.2560x over previous
#include <cuda_runtime.h>
#include <cuda_fp16.h>
#include <cstdint>
#include <cfloat>

#define KC 120
#define DC 128
#define NMAX 262144
#define TILE_M 128
#define SROW 121          // S row stride (floats), odd => conflict-free
#define KCH2 64           // dims per staging chunk
#define XST 72            // f16 row stride (64 + 8 pad) => conflict-free ldmatrix

typedef unsigned long long u64;

// ---------------- device scratch ----------------
__device__ float  g_cent[2][KC * DC];
__device__ float  g_csq[2][KC];
__device__ float  g_sums[KC * DC];
__device__ float  g_counts[KC];
__device__ int    g_labels[2][NMAX];
__device__ double g_acc[2];
// X in plain fp16 (built once per replay); centroids split hi/lo (per iteration)
__device__ __half g_xh[2][NMAX * DC];
__device__ __half g_ch[2][KC * DC];
__device__ __half g_cl[2][KC * DC];

// single dynamic-smem symbol shared by all kernels (cast locally)
extern __shared__ char dyn_smem[];

// ---------------- smem layout (gemm kernel) ----------------
#define OFF_CSQ 0                       // 128 floats
#define OFF_RED 512                     // 8 floats
#define OFF_XH  1024                    // 128 x 72 f16 = 18432 B
#define OFF_CH  (1024 + 18432)
#define OFF_CL  (1024 + 2 * 18432)
#define OFF_S   1024                    // epilogue S overlaps staging
#define GEMM_SMEM (1024 + TILE_M * SROW * 4)   // 62976 B

// m16n8k16 f16 mma, fp32 accumulate
__device__ __forceinline__ void mma16816(float* c, const uint32_t* a,
                                         uint32_t b0, uint32_t b1) {
    asm volatile(
        "mma.sync.aligned.m16n8k16.row.col.f32.f16.f16.f32 "
        "{%0,%1,%2,%3}, {%4,%5,%6,%7}, {%8,%9}, {%0,%1,%2,%3};"
        : "+f"(c[0]), "+f"(c[1]), "+f"(c[2]), "+f"(c[3])
        : "r"(a[0]), "r"(a[1]), "r"(a[2]), "r"(a[3]), "r"(b0), "r"(b1));
}
__device__ __forceinline__ void ldsm_x4(uint32_t* r, uint32_t addr) {
    asm volatile("ldmatrix.sync.aligned.m8n8.x4.shared.b16 {%0,%1,%2,%3}, [%4];"
        : "=r"(r[0]), "=r"(r[1]), "=r"(r[2]), "=r"(r[3]) : "r"(addr));
}

// ================= one-time fp16 conversion of X =================
__global__ __launch_bounds__(256)
void preconvert_kernel(const float* __restrict__ x, int set, int total4) {
    int idx = blockIdx.x * 256 + threadIdx.x;    // float4 index
    if (idx >= total4) return;
    float4 v = ((const float4*)x)[idx];
    __half2* dh = (__half2*)(g_xh[set]) + idx * 2;
    dh[0] = __halves2half2(__float2half_rn(v.x), __float2half_rn(v.y));
    dh[1] = __halves2half2(__float2half_rn(v.z), __float2half_rn(v.w));
}

// ================= tensor-core GEMM + head =================
// dot[p][k] = x16_p (features xset) . c_k (centroids cset, hi+lo split).
// mode 0 (xset==cset): argmin_k (csq[k] - 2*dot) -> g_labels[cset]
// mode 1: CE_i = logsumexp(2.5*dot) - 2.5*dot[lab_i], lab from g_labels[cset] -> g_acc[aidx]
__global__ __launch_bounds__(256, 2)
void gemm_head_kernel(int xset, int cset, int mode, int aidx, int N) {
    char* sm = dyn_smem;
    float*  csq_s = (float*)(sm + OFF_CSQ);
    __half* xh = (__half*)(sm + OFF_XH);
    __half* chh = (__half*)(sm + OFF_CH);
    __half* cll = (__half*)(sm + OFF_CL);
    float*  S  = (float*)(sm + OFF_S);

    int tid = threadIdx.x;
    int lane = tid & 31, g = lane >> 2, t = lane & 3;
    int warp = tid >> 5;
    int wm = warp >> 1;            // 0..3  -> rows wm*32
    int wn = warp & 1;             // 0..1  -> cols wn*64
    int pm = wm * 32;
    int nb = wn * 64;

    if (mode == 0 && tid < KC) csq_s[tid] = g_csq[cset][tid];

    int tile0 = blockIdx.x * TILE_M;

    float acc[2][8][4];
    #pragma unroll
    for (int mi = 0; mi < 2; mi++)
        #pragma unroll
        for (int ni = 0; ni < 8; ni++)
            #pragma unroll
            for (int q = 0; q < 4; q++) acc[mi][ni][q] = 0.0f;

    uint32_t xh_s = (uint32_t)__cvta_generic_to_shared(xh);
    uint32_t ch_s = (uint32_t)__cvta_generic_to_shared(chh);
    uint32_t cl_s = (uint32_t)__cvta_generic_to_shared(cll);

    // ldmatrix per-lane selectors
    int arow  = ((lane >> 3) & 1) * 8 + (lane & 7);   // A x4: rows 0-7/8-15, k0/k8
    int acol8 = ((lane >> 4) & 1) * 8;
    int brow  = ((lane >> 4) & 1) * 8 + (lane & 7);   // B x4: n-rows 0-7/8-15
    int bcol8 = ((lane >> 3) & 1) * 8;                //       k0 / k8

    for (int ch = 0; ch < 2; ch++) {
        int k0 = ch * KCH2;

        // ---- stage: pure uint4 copies (X fp16; C hi/lo) ----
        #pragma unroll
        for (int it = 0; it < 4; it++) {
            int idx = tid + 256 * it;            // 0..1023
            int p = idx >> 3, s = idx & 7;       // row, 16B-slot
            int pc = tile0 + p; if (pc >= N) pc = N - 1;
            *(uint4*)(xh + p * XST + s * 8) =
                *((const uint4*)(g_xh[xset] + (size_t)pc * DC + k0) + s);
            uint4 vh = make_uint4(0u, 0u, 0u, 0u), vl = vh;
            if (p < KC) {
                vh = *((const uint4*)(g_ch[cset] + p * DC + k0) + s);
                vl = *((const uint4*)(g_cl[cset] + p * DC + k0) + s);
            }
            *(uint4*)(chh + p * XST + s * 8) = vh;
            *(uint4*)(cll + p * XST + s * 8) = vl;
        }
        __syncthreads();

        // ---- mma over 4 k-steps of 16 ----
        #pragma unroll
        for (int ks = 0; ks < 4; ks++) {
            int kk = ks * 16;
            uint32_t a[2][4];
            #pragma unroll
            for (int mi = 0; mi < 2; mi++) {
                uint32_t aoff = (uint32_t)(((pm + mi * 16 + arow) * XST + kk + acol8) * 2);
                ldsm_x4(a[mi], xh_s + aoff);
            }
            #pragma unroll
            for (int pr = 0; pr < 4; pr++) {      // pairs of ni
                uint32_t boff = (uint32_t)(((nb + pr * 16 + brow) * XST + kk + bcol8) * 2);
                uint32_t bh[4], bl[4];
                ldsm_x4(bh, ch_s + boff);
                ldsm_x4(bl, cl_s + boff);
                #pragma unroll
                for (int mi = 0; mi < 2; mi++) {
                    mma16816(acc[mi][2 * pr],     a[mi], bh[0], bh[1]);   // x*ch
                    mma16816(acc[mi][2 * pr],     a[mi], bl[0], bl[1]);   // x*cl
                    mma16816(acc[mi][2 * pr + 1], a[mi], bh[2], bh[3]);
                    mma16816(acc[mi][2 * pr + 1], a[mi], bl[2], bl[3]);
                }
            }
        }
        __syncthreads();   // staging region about to be reused
    }

    // ---- write S[p][n] (skip pad cols 120..127: wn==1 && ni==7) ----
    #pragma unroll
    for (int mi = 0; mi < 2; mi++) {
        int p0 = pm + mi * 16 + g;
        #pragma unroll
        for (int ni = 0; ni < 8; ni++) {
            if (wn == 1 && ni == 7) continue;
            int n0 = nb + ni * 8 + 2 * t;
            S[p0 * SROW + n0]           = acc[mi][ni][0];
            S[p0 * SROW + n0 + 1]       = acc[mi][ni][1];
            S[(p0 + 8) * SROW + n0]     = acc[mi][ni][2];
            S[(p0 + 8) * SROW + n0 + 1] = acc[mi][ni][3];
        }
    }
    __syncthreads();

    // ---- head: one thread per point (threads 0..127) ----
    int p = tile0 + tid;
    bool valid = (tid < TILE_M) && (p < N);

    if (mode == 0) {
        if (valid) {
            const float* Sp = S + tid * SROW;
            float best = FLT_MAX;
            int bi = 0;
            #pragma unroll 4
            for (int k = 0; k < KC; k++) {
                float dist = csq_s[k] - 2.0f * Sp[k];
                if (dist < best) { best = dist; bi = k; }   // strict < => first-index ties
            }
            g_labels[cset][p] = bi;
        }
    } else {
        float ce = 0.0f;
        if (valid) {
            const float* Sp = S + tid * SROW;
            int lab = g_labels[cset][p];
            float m = -3.0e38f, ss = 0.0f, lgl = 0.0f;
            #pragma unroll 4
            for (int k = 0; k < KC; k++) {
                float lg = 2.5f * Sp[k];          // / CLD_T = 0.4
                if (k == lab) lgl = lg;
                float nm = fmaxf(m, lg);
                ss = ss * __expf(m - nm) + __expf(lg - nm);
                m = nm;
            }
            ce = m + logf(ss) - lgl;
        }
        #pragma unroll
        for (int o = 16; o > 0; o >>= 1) ce += __shfl_down_sync(0xffffffffu, ce, o);
        float* red = (float*)(sm + OFF_RED);
        if ((tid & 31) == 0) red[tid >> 5] = ce;
        __syncthreads();
        if (tid == 0) {
            float tt = red[0] + red[1] + red[2] + red[3] +
                       red[4] + red[5] + red[6] + red[7];
            atomicAdd(&g_acc[aidx], (double)tt);
        }
    }
}

// ================= centroid init / update (+ fp16 hi/lo split) =================
__global__ void centroid_kernel(const float* __restrict__ x, int set, int mode) {
    int k = blockIdx.x;
    int d = threadIdx.x;
    float c;
    if (mode == 0) {
        c = x[k * DC + d];
    } else {
        float cnt = g_counts[k];
        if (cnt == 0.0f) cnt = 1.0f;
        c = g_sums[k * DC + d] / cnt;
    }
    g_cent[set][k * DC + d] = c;
    __half hc = __float2half_rn(c);
    g_ch[set][k * DC + d] = hc;
    g_cl[set][k * DC + d] = __float2half_rn(c - __half2float(hc));
    g_sums[k * DC + d] = 0.0f;
    if (d == 0) g_counts[k] = 0.0f;

    float v = c * c;
    #pragma unroll
    for (int o = 16; o > 0; o >>= 1) v += __shfl_down_sync(0xffffffffu, v, o);
    __shared__ float rsm[4];
    if ((d & 31) == 0) rsm[d >> 5] = v;
    __syncthreads();
    if (d == 0) g_csq[set][k] = rsm[0] + rsm[1] + rsm[2] + rsm[3];
}

// ================= scatter reduce (batch-32 MLP, smem labels) =================
#define RGRID 148
#define PERMAX 2048
#define REDUCE_SMEM ((2 * KC * DC + 128 + PERMAX) * 4)

__global__ __launch_bounds__(256, 1)
void reduce_kernel(const float* __restrict__ x, int set, int N) {
    float* smf = (float*)dyn_smem;
    float* sumA = smf;                         // KC*DC
    float* sumB = smf + KC * DC;               // KC*DC
    float* scnt = smf + 2 * KC * DC;           // 128 (120 used)
    int*   slab = (int*)(smf + 2 * KC * DC + 128);

    int tid = threadIdx.x;
    for (int i = tid; i < 2 * KC * DC; i += 256) smf[i] = 0.0f;
    for (int i = tid; i < 128; i += 256) scnt[i] = 0.0f;

    const int* __restrict__ lab = g_labels[set];
    int G = gridDim.x;
    int per = (N + G - 1) / G;
    int p0 = blockIdx.x * per;
    int cnt = min(N, p0 + per) - p0;
    if (cnt < 0) cnt = 0;

    for (int i = tid; i < cnt; i += 256) slab[i] = lab[p0 + i];
    __syncthreads();

    int half = tid >> 7;       // 0 or 1
    int d = tid & 127;
    float* mysum = half ? sumB : sumA;
    int mid = cnt >> 1;
    int qs = half ? mid : 0;
    int qe = half ? cnt : mid;

    const float* __restrict__ xb = x + (size_t)p0 * DC + d;
    int q = qs;
    for (; q + 32 <= qe; q += 32) {
        float v[32];
        #pragma unroll
        for (int i = 0; i < 32; i++)
            v[i] = __ldg(xb + (size_t)(q + i) * DC);
        int l[32];
        #pragma unroll
        for (int i = 0; i < 32; i++) l[i] = slab[q + i];
        #pragma unroll
        for (int i = 0; i < 32; i++)
            mysum[l[i] * DC + d] += v[i];
    }
    for (; q < qe; ++q)
        mysum[slab[q] * DC + d] += __ldg(xb + (size_t)q * DC);

    // counts (spread smem atomics over staged labels)
    for (int i = tid; i < cnt; i += 256)
        atomicAdd(&scnt[slab[i]], 1.0f);
    __syncthreads();

    for (int i = tid; i < KC * DC; i += 256)
        atomicAdd(&g_sums[i], sumA[i] + sumB[i]);
    for (int i = tid; i < KC; i += 256)
        atomicAdd(&g_counts[i], scnt[i]);
}

__global__ void zero_acc_kernel() {
    if (threadIdx.x < 2) g_acc[threadIdx.x] = 0.0;
}
__global__ void finalize_kernel(float* out, int N) {
    out[0] = (float)((g_acc[0] + g_acc[1]) / (2.0 * (double)N));
}

// ================= launch =================
extern "C" void kernel_launch(void* const* d_in, const int* in_sizes, int n_in,
                              void* d_out, int out_size) {
    const float* f1 = (const float*)d_in[0];
    const float* f2 = (const float*)d_in[1];
    int N = in_sizes[0] / DC;

    cudaFuncSetAttribute(gemm_head_kernel, cudaFuncAttributeMaxDynamicSharedMemorySize, GEMM_SMEM);
    cudaFuncSetAttribute(reduce_kernel, cudaFuncAttributeMaxDynamicSharedMemorySize, REDUCE_SMEM);

    int ggrid = (N + TILE_M - 1) / TILE_M;
    int total4 = N * DC / 4;
    int pgrid = (total4 + 255) / 256;

    preconvert_kernel<<<pgrid, 256>>>(f1, 0, total4);
    preconvert_kernel<<<pgrid, 256>>>(f2, 1, total4);

    for (int s = 0; s < 2; ++s) {
        const float* x = s ? f2 : f1;
        centroid_kernel<<<KC, DC>>>(x, s, 0);
        for (int it = 0; it < 5; ++it) {
            gemm_head_kernel<<<ggrid, 256, GEMM_SMEM>>>(s, s, 0, 0, N);
            reduce_kernel<<<RGRID, 256, REDUCE_SMEM>>>(x, s, N);
            centroid_kernel<<<KC, DC>>>(nullptr, s, 1);
        }
    }
    zero_acc_kernel<<<1, 32>>>();
    gemm_head_kernel<<<ggrid, 256, GEMM_SMEM>>>(0, 1, 1, 0, N);  // X=f1 vs c2/cl2
    gemm_head_kernel<<<ggrid, 256, GEMM_SMEM>>>(1, 0, 1, 1, N);  // X=f2 vs c1/cl1
    finalize_kernel<<<1, 1>>>((float*)d_out, N);
}

// round 15
// speedup vs baseline: 1.7922x; 1.1411x over previous
#include <cuda_runtime.h>
#include <cuda_fp16.h>
#include <cstdint>
#include <cfloat>

#define KC 120
#define DC 128
#define NMAX 262144
#define TILE_M 128
#define SROW 121          // S row stride (floats), odd => conflict-free
#define KCH2 64           // dims per staging chunk
#define XST 72            // f16 row stride (64 + 8 pad) => conflict-free ldmatrix

typedef unsigned long long u64;

// ---------------- device scratch ----------------
__device__ float  g_cent[2][KC * DC];
__device__ float  g_csq[2][KC];
__device__ float  g_sums[KC * DC];
__device__ float  g_counts[KC];
__device__ int    g_labels[2][NMAX];
__device__ double g_acc[2];
// X and C in plain fp16 (X once per replay; C per iteration)
__device__ __half g_xh[2][NMAX * DC];
__device__ __half g_ch[2][KC * DC];

// single dynamic-smem symbol shared by all kernels (cast locally)
extern __shared__ char dyn_smem[];

// ---------------- smem layout (gemm kernel) ----------------
#define OFF_CSQ 0                       // 128 floats
#define OFF_RED 512                     // 8 floats
#define OFF_XH  1024                    // 128 x 72 f16 = 18432 B
#define OFF_CH  (1024 + 18432)
#define OFF_S   1024                    // epilogue S overlaps staging
#define GEMM_SMEM (1024 + TILE_M * SROW * 4)   // 62976 B

// m16n8k16 f16 mma, fp32 accumulate
__device__ __forceinline__ void mma16816(float* c, const uint32_t* a,
                                         uint32_t b0, uint32_t b1) {
    asm volatile(
        "mma.sync.aligned.m16n8k16.row.col.f32.f16.f16.f32 "
        "{%0,%1,%2,%3}, {%4,%5,%6,%7}, {%8,%9}, {%0,%1,%2,%3};"
        : "+f"(c[0]), "+f"(c[1]), "+f"(c[2]), "+f"(c[3])
        : "r"(a[0]), "r"(a[1]), "r"(a[2]), "r"(a[3]), "r"(b0), "r"(b1));
}
__device__ __forceinline__ void ldsm_x4(uint32_t* r, uint32_t addr) {
    asm volatile("ldmatrix.sync.aligned.m8n8.x4.shared.b16 {%0,%1,%2,%3}, [%4];"
        : "=r"(r[0]), "=r"(r[1]), "=r"(r[2]), "=r"(r[3]) : "r"(addr));
}

// ================= one-time fp16 conversion of X =================
__global__ __launch_bounds__(256)
void preconvert_kernel(const float* __restrict__ x, int set, int total4) {
    int idx = blockIdx.x * 256 + threadIdx.x;    // float4 index
    if (idx >= total4) return;
    float4 v = ((const float4*)x)[idx];
    __half2* dh = (__half2*)(g_xh[set]) + idx * 2;
    dh[0] = __halves2half2(__float2half_rn(v.x), __float2half_rn(v.y));
    dh[1] = __halves2half2(__float2half_rn(v.z), __float2half_rn(v.w));
}

// ================= tensor-core GEMM + head (pure fp16, fp32 acc) =================
// dot[p][k] = x16_p (features xset) . c16_k (centroids cset).
// mode 0 (xset==cset): argmin_k (csq[k] - 2*dot) -> g_labels[cset]
// mode 1: CE_i = logsumexp(2.5*dot) - 2.5*dot[lab_i], lab from g_labels[cset] -> g_acc[aidx]
__global__ __launch_bounds__(256, 2)
void gemm_head_kernel(int xset, int cset, int mode, int aidx, int N) {
    char* sm = dyn_smem;
    float*  csq_s = (float*)(sm + OFF_CSQ);
    __half* xh = (__half*)(sm + OFF_XH);
    __half* chh = (__half*)(sm + OFF_CH);
    float*  S  = (float*)(sm + OFF_S);

    int tid = threadIdx.x;
    int lane = tid & 31, g = lane >> 2, t = lane & 3;
    int warp = tid >> 5;
    int wm = warp >> 1;            // 0..3  -> rows wm*32
    int wn = warp & 1;             // 0..1  -> cols wn*64
    int pm = wm * 32;
    int nb = wn * 64;

    if (mode == 0 && tid < KC) csq_s[tid] = g_csq[cset][tid];

    int tile0 = blockIdx.x * TILE_M;

    float acc[2][8][4];
    #pragma unroll
    for (int mi = 0; mi < 2; mi++)
        #pragma unroll
        for (int ni = 0; ni < 8; ni++)
            #pragma unroll
            for (int q = 0; q < 4; q++) acc[mi][ni][q] = 0.0f;

    uint32_t xh_s = (uint32_t)__cvta_generic_to_shared(xh);
    uint32_t ch_s = (uint32_t)__cvta_generic_to_shared(chh);

    // ldmatrix per-lane selectors
    int arow  = ((lane >> 3) & 1) * 8 + (lane & 7);   // A x4: rows 0-7/8-15, k0/k8
    int acol8 = ((lane >> 4) & 1) * 8;
    int brow  = ((lane >> 4) & 1) * 8 + (lane & 7);   // B x4: n-rows 0-7/8-15
    int bcol8 = ((lane >> 3) & 1) * 8;                //       k0 / k8

    for (int ch = 0; ch < 2; ch++) {
        int k0 = ch * KCH2;

        // ---- stage: pure uint4 copies ----
        #pragma unroll
        for (int it = 0; it < 4; it++) {
            int idx = tid + 256 * it;            // 0..1023
            int p = idx >> 3, s = idx & 7;       // row, 16B-slot
            int pc = tile0 + p; if (pc >= N) pc = N - 1;
            *(uint4*)(xh + p * XST + s * 8) =
                *((const uint4*)(g_xh[xset] + (size_t)pc * DC + k0) + s);
            uint4 vh = make_uint4(0u, 0u, 0u, 0u);
            if (p < KC)
                vh = *((const uint4*)(g_ch[cset] + p * DC + k0) + s);
            *(uint4*)(chh + p * XST + s * 8) = vh;
        }
        __syncthreads();

        // ---- mma over 4 k-steps of 16 ----
        #pragma unroll
        for (int ks = 0; ks < 4; ks++) {
            int kk = ks * 16;
            uint32_t a[2][4];
            #pragma unroll
            for (int mi = 0; mi < 2; mi++) {
                uint32_t aoff = (uint32_t)(((pm + mi * 16 + arow) * XST + kk + acol8) * 2);
                ldsm_x4(a[mi], xh_s + aoff);
            }
            #pragma unroll
            for (int pr = 0; pr < 4; pr++) {      // pairs of ni
                uint32_t boff = (uint32_t)(((nb + pr * 16 + brow) * XST + kk + bcol8) * 2);
                uint32_t bh[4];
                ldsm_x4(bh, ch_s + boff);
                #pragma unroll
                for (int mi = 0; mi < 2; mi++) {
                    mma16816(acc[mi][2 * pr],     a[mi], bh[0], bh[1]);
                    mma16816(acc[mi][2 * pr + 1], a[mi], bh[2], bh[3]);
                }
            }
        }
        __syncthreads();   // staging region about to be reused
    }

    // ---- write S[p][n] (skip pad cols 120..127: wn==1 && ni==7) ----
    #pragma unroll
    for (int mi = 0; mi < 2; mi++) {
        int p0 = pm + mi * 16 + g;
        #pragma unroll
        for (int ni = 0; ni < 8; ni++) {
            if (wn == 1 && ni == 7) continue;
            int n0 = nb + ni * 8 + 2 * t;
            S[p0 * SROW + n0]           = acc[mi][ni][0];
            S[p0 * SROW + n0 + 1]       = acc[mi][ni][1];
            S[(p0 + 8) * SROW + n0]     = acc[mi][ni][2];
            S[(p0 + 8) * SROW + n0 + 1] = acc[mi][ni][3];
        }
    }
    __syncthreads();

    // ---- head: one thread per point (threads 0..127) ----
    int p = tile0 + tid;
    bool valid = (tid < TILE_M) && (p < N);

    if (mode == 0) {
        if (valid) {
            const float* Sp = S + tid * SROW;
            float best = FLT_MAX;
            int bi = 0;
            #pragma unroll 4
            for (int k = 0; k < KC; k++) {
                float dist = csq_s[k] - 2.0f * Sp[k];
                if (dist < best) { best = dist; bi = k; }   // strict < => first-index ties
            }
            g_labels[cset][p] = bi;
        }
    } else {
        float ce = 0.0f;
        if (valid) {
            const float* Sp = S + tid * SROW;
            int lab = g_labels[cset][p];
            float m = -3.0e38f, ss = 0.0f, lgl = 0.0f;
            #pragma unroll 4
            for (int k = 0; k < KC; k++) {
                float lg = 2.5f * Sp[k];          // / CLD_T = 0.4
                if (k == lab) lgl = lg;
                float nm = fmaxf(m, lg);
                ss = ss * __expf(m - nm) + __expf(lg - nm);
                m = nm;
            }
            ce = m + logf(ss) - lgl;
        }
        #pragma unroll
        for (int o = 16; o > 0; o >>= 1) ce += __shfl_down_sync(0xffffffffu, ce, o);
        float* red = (float*)(sm + OFF_RED);
        if ((tid & 31) == 0) red[tid >> 5] = ce;
        __syncthreads();
        if (tid == 0) {
            float tt = red[0] + red[1] + red[2] + red[3] +
                       red[4] + red[5] + red[6] + red[7];
            atomicAdd(&g_acc[aidx], (double)tt);
        }
    }
}

// ================= centroid init / update (+ fp16 convert) =================
__global__ void centroid_kernel(const float* __restrict__ x, int set, int mode) {
    int k = blockIdx.x;
    int d = threadIdx.x;
    float c;
    if (mode == 0) {
        c = x[k * DC + d];
    } else {
        float cnt = g_counts[k];
        if (cnt == 0.0f) cnt = 1.0f;
        c = g_sums[k * DC + d] / cnt;
    }
    g_cent[set][k * DC + d] = c;
    g_ch[set][k * DC + d] = __float2half_rn(c);
    g_sums[k * DC + d] = 0.0f;
    if (d == 0) g_counts[k] = 0.0f;

    float v = c * c;
    #pragma unroll
    for (int o = 16; o > 0; o >>= 1) v += __shfl_down_sync(0xffffffffu, v, o);
    __shared__ float rsm[4];
    if ((d & 31) == 0) rsm[d >> 5] = v;
    __syncthreads();
    if (d == 0) g_csq[set][k] = rsm[0] + rsm[1] + rsm[2] + rsm[3];
}

// ================= scatter reduce (batch-32 MLP, smem labels) =================
#define RGRID 148
#define PERMAX 2048
#define REDUCE_SMEM ((2 * KC * DC + 128 + PERMAX) * 4)

__global__ __launch_bounds__(256, 1)
void reduce_kernel(const float* __restrict__ x, int set, int N) {
    float* smf = (float*)dyn_smem;
    float* sumA = smf;                         // KC*DC
    float* sumB = smf + KC * DC;               // KC*DC
    float* scnt = smf + 2 * KC * DC;           // 128 (120 used)
    int*   slab = (int*)(smf + 2 * KC * DC + 128);

    int tid = threadIdx.x;
    for (int i = tid; i < 2 * KC * DC; i += 256) smf[i] = 0.0f;
    for (int i = tid; i < 128; i += 256) scnt[i] = 0.0f;

    const int* __restrict__ lab = g_labels[set];
    int G = gridDim.x;
    int per = (N + G - 1) / G;
    int p0 = blockIdx.x * per;
    int cnt = min(N, p0 + per) - p0;
    if (cnt < 0) cnt = 0;

    for (int i = tid; i < cnt; i += 256) slab[i] = lab[p0 + i];
    __syncthreads();

    int half = tid >> 7;       // 0 or 1
    int d = tid & 127;
    float* mysum = half ? sumB : sumA;
    int mid = cnt >> 1;
    int qs = half ? mid : 0;
    int qe = half ? cnt : mid;

    const float* __restrict__ xb = x + (size_t)p0 * DC + d;
    int q = qs;
    for (; q + 32 <= qe; q += 32) {
        float v[32];
        #pragma unroll
        for (int i = 0; i < 32; i++)
            v[i] = __ldg(xb + (size_t)(q + i) * DC);
        int l[32];
        #pragma unroll
        for (int i = 0; i < 32; i++) l[i] = slab[q + i];
        #pragma unroll
        for (int i = 0; i < 32; i++)
            mysum[l[i] * DC + d] += v[i];
    }
    for (; q < qe; ++q)
        mysum[slab[q] * DC + d] += __ldg(xb + (size_t)q * DC);

    // counts (spread smem atomics over staged labels)
    for (int i = tid; i < cnt; i += 256)
        atomicAdd(&scnt[slab[i]], 1.0f);
    __syncthreads();

    for (int i = tid; i < KC * DC; i += 256)
        atomicAdd(&g_sums[i], sumA[i] + sumB[i]);
    for (int i = tid; i < KC; i += 256)
        atomicAdd(&g_counts[i], scnt[i]);
}

__global__ void zero_acc_kernel() {
    if (threadIdx.x < 2) g_acc[threadIdx.x] = 0.0;
}
__global__ void finalize_kernel(float* out, int N) {
    out[0] = (float)((g_acc[0] + g_acc[1]) / (2.0 * (double)N));
}

// ================= launch =================
extern "C" void kernel_launch(void* const* d_in, const int* in_sizes, int n_in,
                              void* d_out, int out_size) {
    const float* f1 = (const float*)d_in[0];
    const float* f2 = (const float*)d_in[1];
    int N = in_sizes[0] / DC;

    cudaFuncSetAttribute(gemm_head_kernel, cudaFuncAttributeMaxDynamicSharedMemorySize, GEMM_SMEM);
    cudaFuncSetAttribute(reduce_kernel, cudaFuncAttributeMaxDynamicSharedMemorySize, REDUCE_SMEM);

    int ggrid = (N + TILE_M - 1) / TILE_M;
    int total4 = N * DC / 4;
    int pgrid = (total4 + 255) / 256;

    preconvert_kernel<<<pgrid, 256>>>(f1, 0, total4);
    preconvert_kernel<<<pgrid, 256>>>(f2, 1, total4);

    for (int s = 0; s < 2; ++s) {
        const float* x = s ? f2 : f1;
        centroid_kernel<<<KC, DC>>>(x, s, 0);
        for (int it = 0; it < 5; ++it) {
            gemm_head_kernel<<<ggrid, 256, GEMM_SMEM>>>(s, s, 0, 0, N);
            reduce_kernel<<<RGRID, 256, REDUCE_SMEM>>>(x, s, N);
            centroid_kernel<<<KC, DC>>>(nullptr, s, 1);
        }
    }
    zero_acc_kernel<<<1, 32>>>();
    gemm_head_kernel<<<ggrid, 256, GEMM_SMEM>>>(0, 1, 1, 0, N);  // X=f1 vs c2/cl2
    gemm_head_kernel<<<ggrid, 256, GEMM_SMEM>>>(1, 0, 1, 1, N);  // X=f2 vs c1/cl1
    finalize_kernel<<<1, 1>>>((float*)d_out, N);
}